// round 1
// baseline (speedup 1.0000x reference)
#include <cuda_runtime.h>
#include <math.h>

// ---------------- problem constants ----------------
#define BB    4
#define LL    2048
#define HH    1024
#define NQH   8
#define NKVH  2
#define DD    256
#define II    3584
#define VV    16384
#define NTOK  (BB*LL)          // 8192
#define FMIN  (-3.402823466e38f)

// ---------------- static scratch (no cudaMalloc allowed) ----------------
__device__ float g_xcat [ (size_t)NTOK * 2 * HH ];          // 67 MB
__device__ float g_x0   [ (size_t)NTOK * HH ];              // fc out / residual 1
__device__ float g_xn   [ (size_t)NTOK * HH ];
__device__ float g_qg   [ (size_t)NTOK * 4096 ];            // q+gate packed
__device__ float g_kbuf [ (size_t)NTOK * 512 ];
__device__ float g_vbuf [ (size_t)NTOK * 512 ];
__device__ float g_q    [ (size_t)BB * NQH * LL * DD ];
__device__ float g_krep [ (size_t)BB * NQH * LL * DD ];     // GQA-replicated
__device__ float g_vrep [ (size_t)BB * NQH * LL * DD ];
__device__ float g_scores[ (size_t)BB * NQH * LL * LL ];    // 537 MB
__device__ float g_attno[ (size_t)BB * NQH * LL * DD ];
__device__ float g_ao   [ (size_t)NTOK * 2048 ];
__device__ float g_x1   [ (size_t)NTOK * HH ];
__device__ float g_xn2  [ (size_t)NTOK * HH ];
__device__ float g_gbuf [ (size_t)NTOK * II ];
__device__ float g_ubuf [ (size_t)NTOK * II ];
__device__ float g_x2   [ (size_t)NTOK * HH ];
__device__ float g_xn3  [ (size_t)NTOK * HH ];

// ---------------- block reduce helpers (256 threads) ----------------
__device__ __forceinline__ float blk_sum(float v) {
    __shared__ float sh[8];
    __shared__ float res;
    #pragma unroll
    for (int o = 16; o; o >>= 1) v += __shfl_xor_sync(0xffffffffu, v, o);
    if ((threadIdx.x & 31) == 0) sh[threadIdx.x >> 5] = v;
    __syncthreads();
    if (threadIdx.x < 32) {
        float x = (threadIdx.x < 8) ? sh[threadIdx.x] : 0.f;
        #pragma unroll
        for (int o = 4; o; o >>= 1) x += __shfl_xor_sync(0xffffffffu, x, o);
        if (threadIdx.x == 0) res = x;
    }
    __syncthreads();
    return res;
}

__device__ __forceinline__ float blk_max(float v) {
    __shared__ float sh[8];
    __shared__ float res;
    #pragma unroll
    for (int o = 16; o; o >>= 1) v = fmaxf(v, __shfl_xor_sync(0xffffffffu, v, o));
    if ((threadIdx.x & 31) == 0) sh[threadIdx.x >> 5] = v;
    __syncthreads();
    if (threadIdx.x < 32) {
        float x = (threadIdx.x < 8) ? sh[threadIdx.x] : -INFINITY;
        #pragma unroll
        for (int o = 4; o; o >>= 1) x = fmaxf(x, __shfl_xor_sync(0xffffffffu, x, o));
        if (threadIdx.x == 0) res = x;
    }
    __syncthreads();
    return res;
}

// ---------------- rmsnorm: one block per token ----------------
__global__ void rmsnorm_kernel(const float* __restrict__ in, const float* __restrict__ w,
                               float* __restrict__ out, int width, long out_stride) {
    long t = blockIdx.x;
    const float* x = in + t * width;
    float* y = out + t * out_stride;
    float ss = 0.f;
    for (int i = threadIdx.x; i < width; i += 256) { float v = x[i]; ss = fmaf(v, v, ss); }
    float tot = blk_sum(ss);
    float rms = rsqrtf(tot / (float)width + 1e-6f);
    for (int i = threadIdx.x; i < width; i += 256) y[i] = x[i] * rms * w[i];
}

// ---------------- SGEMM  C[M,N] = A[M,K] * B[N,K]^T  (+ epilogues) ----------------
// epilogue 0: plain   1: C = acc + R   2: scores (acc*scale, causal mask)
#define GBM 128
#define GBN 128
#define GBK 8

__global__ __launch_bounds__(256, 2)
void gemm_nt_kernel(const float* __restrict__ A, const float* __restrict__ B,
                    float* __restrict__ C, const float* __restrict__ R,
                    int M, int N, int K,
                    long batchA, long batchB, long batchC,
                    int epilogue, float scale) {
    int z = blockIdx.z;
    const float* Ab = A + (long)z * batchA;
    const float* Bb = B + (long)z * batchB;
    float*       Cb = C + (long)z * batchC;
    int m0 = blockIdx.y * GBM;
    int n0 = blockIdx.x * GBN;

    if (epilogue == 2 && n0 > m0 + GBM - 1) {   // fully masked causal block
        float4 f = make_float4(FMIN, FMIN, FMIN, FMIN);
        for (int i = threadIdx.x; i < (GBM * GBN) / 4; i += 256) {
            int mm = i >> 5;
            int nn = (i & 31) << 2;
            *(float4*)&Cb[(long)(m0 + mm) * N + n0 + nn] = f;
        }
        return;
    }

    __shared__ float As[GBK][GBM + 4];
    __shared__ float Bs[GBK][GBN + 4];

    int tid = threadIdx.x;
    int lr = tid >> 1;
    int lk = (tid & 1) * 4;

    const float* Aptr = Ab + (long)(m0 + lr) * K + lk;
    const float* Bptr = Bb + (long)(n0 + lr) * K + lk;

    int ty = tid >> 4, tx = tid & 15;
    float acc[8][8];
    #pragma unroll
    for (int i = 0; i < 8; i++)
        #pragma unroll
        for (int j = 0; j < 8; j++) acc[i][j] = 0.f;

    float4 ar = *(const float4*)Aptr;
    float4 br = *(const float4*)Bptr;

    int ntiles = K / GBK;
    for (int t = 0; t < ntiles; ++t) {
        As[lk + 0][lr] = ar.x; As[lk + 1][lr] = ar.y; As[lk + 2][lr] = ar.z; As[lk + 3][lr] = ar.w;
        Bs[lk + 0][lr] = br.x; Bs[lk + 1][lr] = br.y; Bs[lk + 2][lr] = br.z; Bs[lk + 3][lr] = br.w;
        __syncthreads();
        if (t + 1 < ntiles) {
            ar = *(const float4*)(Aptr + (long)(t + 1) * GBK);
            br = *(const float4*)(Bptr + (long)(t + 1) * GBK);
        }
        #pragma unroll
        for (int kk = 0; kk < GBK; ++kk) {
            float a[8], b[8];
            #pragma unroll
            for (int i = 0; i < 8; i++) a[i] = As[kk][ty * 8 + i];
            #pragma unroll
            for (int j = 0; j < 8; j++) b[j] = Bs[kk][tx * 8 + j];
            #pragma unroll
            for (int i = 0; i < 8; i++)
                #pragma unroll
                for (int j = 0; j < 8; j++)
                    acc[i][j] = fmaf(a[i], b[j], acc[i][j]);
        }
        __syncthreads();
    }

    #pragma unroll
    for (int i = 0; i < 8; i++) {
        int m = m0 + ty * 8 + i;
        long rowoff = (long)m * N + n0 + tx * 8;
        #pragma unroll
        for (int j = 0; j < 8; j++) {
            float v = acc[i][j];
            if (epilogue == 1) v += R[rowoff + j];
            else if (epilogue == 2) {
                v *= scale;
                if (n0 + tx * 8 + j > m) v = FMIN;
            }
            Cb[rowoff + j] = v;
        }
    }
}

// ---------------- SGEMM  C[M,N] = A[M,K] * B[K,N]  (for P@V, causal K-limit) ----------------
__global__ __launch_bounds__(256, 2)
void gemm_nn_kernel(const float* __restrict__ A, const float* __restrict__ B,
                    float* __restrict__ C,
                    int M, int N, int K,
                    long batchA, long batchB, long batchC,
                    int klimit_causal) {
    int z = blockIdx.z;
    const float* Ab = A + (long)z * batchA;
    const float* Bb = B + (long)z * batchB;
    float*       Cb = C + (long)z * batchC;
    int m0 = blockIdx.y * GBM;
    int n0 = blockIdx.x * GBN;

    int Keff = K;
    if (klimit_causal) Keff = min(K, m0 + GBM);

    __shared__ float As[GBK][GBM + 4];
    __shared__ float Bs[GBK][GBN + 4];

    int tid = threadIdx.x;
    int lr = tid >> 1;
    int lk = (tid & 1) * 4;
    int lbk = tid >> 5;           // 0..7
    int lbn = (tid & 31) * 4;     // 0..124

    const float* Aptr = Ab + (long)(m0 + lr) * K + lk;
    const float* Bptr = Bb + (long)lbk * N + n0 + lbn;

    int ty = tid >> 4, tx = tid & 15;
    float acc[8][8];
    #pragma unroll
    for (int i = 0; i < 8; i++)
        #pragma unroll
        for (int j = 0; j < 8; j++) acc[i][j] = 0.f;

    float4 ar = *(const float4*)Aptr;
    float4 br = *(const float4*)Bptr;

    int ntiles = Keff / GBK;
    for (int t = 0; t < ntiles; ++t) {
        As[lk + 0][lr] = ar.x; As[lk + 1][lr] = ar.y; As[lk + 2][lr] = ar.z; As[lk + 3][lr] = ar.w;
        *(float4*)&Bs[lbk][lbn] = br;
        __syncthreads();
        if (t + 1 < ntiles) {
            ar = *(const float4*)(Aptr + (long)(t + 1) * GBK);
            br = *(const float4*)(Bptr + (long)(t + 1) * GBK * N);
        }
        #pragma unroll
        for (int kk = 0; kk < GBK; ++kk) {
            float a[8], b[8];
            #pragma unroll
            for (int i = 0; i < 8; i++) a[i] = As[kk][ty * 8 + i];
            #pragma unroll
            for (int j = 0; j < 8; j++) b[j] = Bs[kk][tx * 8 + j];
            #pragma unroll
            for (int i = 0; i < 8; i++)
                #pragma unroll
                for (int j = 0; j < 8; j++)
                    acc[i][j] = fmaf(a[i], b[j], acc[i][j]);
        }
        __syncthreads();
    }

    #pragma unroll
    for (int i = 0; i < 8; i++) {
        long rowoff = (long)(m0 + ty * 8 + i) * N + n0 + tx * 8;
        #pragma unroll
        for (int j = 0; j < 8; j++) Cb[rowoff + j] = acc[i][j];
    }
}

// ---------------- Q head post-process: rmsnorm(D=256) + RoPE, scatter ----------------
__global__ void qpost_kernel(const float* __restrict__ qg, const float* __restrict__ qn_w,
                             float* __restrict__ qdst) {
    int t = blockIdx.x;               // token
    int h = blockIdx.y;               // q head
    int b = t / LL, l = t % LL;
    const float* src = qg + (long)t * 4096 + h * 512;
    int tid = threadIdx.x;            // 256 = D
    float v = src[tid];
    float tot = blk_sum(v * v);
    float rms = rsqrtf(tot / (float)DD + 1e-6f);
    __shared__ float sq[DD];
    sq[tid] = v * rms * qn_w[tid];
    __syncthreads();
    if (tid < 32) {
        double inv = exp(-((double)(2 * tid) / 64.0) * log(1.0e7));
        double fr = (double)l * inv;
        double c = cos(fr), s = sin(fr);
        float x0 = sq[2 * tid], x1 = sq[2 * tid + 1];
        sq[2 * tid]     = (float)((double)x0 * c - (double)x1 * s);
        sq[2 * tid + 1] = (float)((double)x0 * s + (double)x1 * c);
    }
    __syncthreads();
    qdst[(((long)(b * NQH + h)) * LL + l) * DD + tid] = sq[tid];
}

// ---------------- K head post-process: rmsnorm + RoPE + GQA-replicate x4 ----------------
__global__ void kpost_kernel(const float* __restrict__ kbuf, const float* __restrict__ kn_w,
                             float* __restrict__ kdst) {
    int t = blockIdx.x;
    int h = blockIdx.y;               // kv head (0..1)
    int b = t / LL, l = t % LL;
    const float* src = kbuf + (long)t * 512 + h * 256;
    int tid = threadIdx.x;
    float v = src[tid];
    float tot = blk_sum(v * v);
    float rms = rsqrtf(tot / (float)DD + 1e-6f);
    __shared__ float sq[DD];
    sq[tid] = v * rms * kn_w[tid];
    __syncthreads();
    if (tid < 32) {
        double inv = exp(-((double)(2 * tid) / 64.0) * log(1.0e7));
        double fr = (double)l * inv;
        double c = cos(fr), s = sin(fr);
        float x0 = sq[2 * tid], x1 = sq[2 * tid + 1];
        sq[2 * tid]     = (float)((double)x0 * c - (double)x1 * s);
        sq[2 * tid + 1] = (float)((double)x0 * s + (double)x1 * c);
    }
    __syncthreads();
    float val = sq[tid];
    #pragma unroll
    for (int r = 0; r < 4; ++r)
        kdst[(((long)(b * NQH + h * 4 + r)) * LL + l) * DD + tid] = val;
}

// ---------------- V GQA replicate ----------------
__global__ void vrep_kernel(const float* __restrict__ vbuf, float* __restrict__ vdst) {
    int t = blockIdx.x;
    int h = blockIdx.y;
    int b = t / LL, l = t % LL;
    int tid = threadIdx.x;
    float v = vbuf[(long)t * 512 + h * 256 + tid];
    #pragma unroll
    for (int r = 0; r < 4; ++r)
        vdst[(((long)(b * NQH + h * 4 + r)) * LL + l) * DD + tid] = v;
}

// ---------------- row softmax over L=2048 ----------------
__global__ void softmax_kernel(float* __restrict__ scores) {
    int q = blockIdx.x;
    int z = blockIdx.y;
    float* row = scores + ((long)z * LL + q) * LL;
    float vals[8];
    float mx = -INFINITY;
    #pragma unroll
    for (int i = 0; i < 8; i++) {
        vals[i] = row[threadIdx.x + i * 256];
        mx = fmaxf(mx, vals[i]);
    }
    mx = blk_max(mx);
    float sum = 0.f;
    #pragma unroll
    for (int i = 0; i < 8; i++) { vals[i] = __expf(vals[i] - mx); sum += vals[i]; }
    sum = blk_sum(sum);
    float invs = 1.f / sum;
    #pragma unroll
    for (int i = 0; i < 8; i++) row[threadIdx.x + i * 256] = vals[i] * invs;
}

// ---------------- gather attn out + sigmoid gate ----------------
__global__ void gather_gate_kernel(const float* __restrict__ attno,
                                   const float* __restrict__ qg,
                                   float* __restrict__ ao) {
    long i = (long)blockIdx.x * 256 + threadIdx.x;   // over NTOK*2048
    int t = (int)(i >> 11);
    int c = (int)(i & 2047);
    int h = c >> 8, d = c & 255;
    int b = t / LL, l = t % LL;
    float o = attno[(((long)(b * NQH + h)) * LL + l) * DD + d];
    float gate = qg[(long)t * 4096 + h * 512 + 256 + d];
    ao[i] = o * (1.f / (1.f + expf(-gate)));
}

// ---------------- silu(g) * u (in place into g) ----------------
__global__ void silu_mul_kernel(float* __restrict__ g, const float* __restrict__ u, long n) {
    long i = (long)blockIdx.x * 256 + threadIdx.x;
    if (i < n) {
        float x = g[i];
        g[i] = x * (1.f / (1.f + expf(-x))) * u[i];
    }
}

// ---------------- launch ----------------
extern "C" void kernel_launch(void* const* d_in, const int* in_sizes, int n_in,
                              void* d_out, int out_size) {
    (void)in_sizes; (void)n_in; (void)out_size;
    const float* embeddings = (const float*)d_in[0];
    const float* hidden     = (const float*)d_in[1];
    const float* pre_emb_w  = (const float*)d_in[2];
    const float* pre_hid_w  = (const float*)d_in[3];
    const float* fc_w       = (const float*)d_in[4];
    const float* in_ln_w    = (const float*)d_in[5];
    const float* q_w        = (const float*)d_in[6];
    const float* k_w        = (const float*)d_in[7];
    const float* v_w        = (const float*)d_in[8];
    const float* o_w        = (const float*)d_in[9];
    const float* qn_w       = (const float*)d_in[10];
    const float* kn_w       = (const float*)d_in[11];
    const float* post_ln_w  = (const float*)d_in[12];
    const float* gate_w     = (const float*)d_in[13];
    const float* up_w       = (const float*)d_in[14];
    const float* down_w     = (const float*)d_in[15];
    const float* norm_w     = (const float*)d_in[16];
    const float* lm_w       = (const float*)d_in[17];
    float* out = (float*)d_out;

    static float *p_xcat = nullptr, *p_x0, *p_xn, *p_qg, *p_kbuf, *p_vbuf,
                 *p_q, *p_krep, *p_vrep, *p_scores, *p_attno, *p_ao,
                 *p_x1, *p_xn2, *p_gbuf, *p_ubuf, *p_x2, *p_xn3;
    if (!p_xcat) {
        cudaGetSymbolAddress((void**)&p_xcat,  g_xcat);
        cudaGetSymbolAddress((void**)&p_x0,    g_x0);
        cudaGetSymbolAddress((void**)&p_xn,    g_xn);
        cudaGetSymbolAddress((void**)&p_qg,    g_qg);
        cudaGetSymbolAddress((void**)&p_kbuf,  g_kbuf);
        cudaGetSymbolAddress((void**)&p_vbuf,  g_vbuf);
        cudaGetSymbolAddress((void**)&p_q,     g_q);
        cudaGetSymbolAddress((void**)&p_krep,  g_krep);
        cudaGetSymbolAddress((void**)&p_vrep,  g_vrep);
        cudaGetSymbolAddress((void**)&p_scores,g_scores);
        cudaGetSymbolAddress((void**)&p_attno, g_attno);
        cudaGetSymbolAddress((void**)&p_ao,    g_ao);
        cudaGetSymbolAddress((void**)&p_x1,    g_x1);
        cudaGetSymbolAddress((void**)&p_xn2,   g_xn2);
        cudaGetSymbolAddress((void**)&p_gbuf,  g_gbuf);
        cudaGetSymbolAddress((void**)&p_ubuf,  g_ubuf);
        cudaGetSymbolAddress((void**)&p_x2,    g_x2);
        cudaGetSymbolAddress((void**)&p_xn3,   g_xn3);
    }

    // 1. pre-norms + concat -> xcat [NTOK, 2048]
    rmsnorm_kernel<<<NTOK, 256>>>(embeddings, pre_emb_w, p_xcat,        HH, 2 * HH);
    rmsnorm_kernel<<<NTOK, 256>>>(hidden,     pre_hid_w, p_xcat + HH,   HH, 2 * HH);

    // 2. fc: x0 = xcat @ fc_w^T   [NTOK,1024]
    gemm_nt_kernel<<<dim3(HH / GBN, NTOK / GBM, 1), 256>>>(
        p_xcat, fc_w, p_x0, nullptr, NTOK, HH, 2 * HH, 0, 0, 0, 0, 1.f);

    // 3. in_ln
    rmsnorm_kernel<<<NTOK, 256>>>(p_x0, in_ln_w, p_xn, HH, HH);

    // 4. q/k/v projections
    gemm_nt_kernel<<<dim3(4096 / GBN, NTOK / GBM, 1), 256>>>(
        p_xn, q_w, p_qg, nullptr, NTOK, 4096, HH, 0, 0, 0, 0, 1.f);
    gemm_nt_kernel<<<dim3(512 / GBN, NTOK / GBM, 1), 256>>>(
        p_xn, k_w, p_kbuf, nullptr, NTOK, 512, HH, 0, 0, 0, 0, 1.f);
    gemm_nt_kernel<<<dim3(512 / GBN, NTOK / GBM, 1), 256>>>(
        p_xn, v_w, p_vbuf, nullptr, NTOK, 512, HH, 0, 0, 0, 0, 1.f);

    // 5. head-norm + rope + layout
    qpost_kernel<<<dim3(NTOK, NQH), 256>>>(p_qg, qn_w, p_q);
    kpost_kernel<<<dim3(NTOK, NKVH), 256>>>(p_kbuf, kn_w, p_krep);
    vrep_kernel <<<dim3(NTOK, NKVH), 256>>>(p_vbuf, p_vrep);

    // 6. scores = Q @ K^T * 1/16 with causal mask   batched (32)
    gemm_nt_kernel<<<dim3(LL / GBN, LL / GBM, BB * NQH), 256>>>(
        p_q, p_krep, p_scores, nullptr, LL, LL, DD,
        (long)LL * DD, (long)LL * DD, (long)LL * LL, 2, 0.0625f);

    // 7. softmax
    softmax_kernel<<<dim3(LL, BB * NQH), 256>>>(p_scores);

    // 8. attno = P @ V   batched, causal K-limit
    gemm_nn_kernel<<<dim3(DD / GBN, LL / GBM, BB * NQH), 256>>>(
        p_scores, p_vrep, p_attno, LL, DD, LL,
        (long)LL * LL, (long)LL * DD, (long)LL * DD, 1);

    // 9. gather + gate
    gather_gate_kernel<<<(NTOK * 2048) / 256, 256>>>(p_attno, p_qg, p_ao);

    // 10. o proj + residual -> x1
    gemm_nt_kernel<<<dim3(HH / GBN, NTOK / GBM, 1), 256>>>(
        p_ao, o_w, p_x1, p_x0, NTOK, HH, 2048, 0, 0, 0, 1, 1.f);

    // 11. post_ln
    rmsnorm_kernel<<<NTOK, 256>>>(p_x1, post_ln_w, p_xn2, HH, HH);

    // 12. MLP gate / up
    gemm_nt_kernel<<<dim3(II / GBN, NTOK / GBM, 1), 256>>>(
        p_xn2, gate_w, p_gbuf, nullptr, NTOK, II, HH, 0, 0, 0, 0, 1.f);
    gemm_nt_kernel<<<dim3(II / GBN, NTOK / GBM, 1), 256>>>(
        p_xn2, up_w, p_ubuf, nullptr, NTOK, II, HH, 0, 0, 0, 0, 1.f);

    // 13. silu * up
    silu_mul_kernel<<<((long)NTOK * II) / 256, 256>>>(p_gbuf, p_ubuf, (long)NTOK * II);

    // 14. down + residual -> x2
    gemm_nt_kernel<<<dim3(HH / GBN, NTOK / GBM, 1), 256>>>(
        p_gbuf, down_w, p_x2, p_x1, NTOK, HH, II, 0, 0, 0, 1, 1.f);

    // 15. final norm
    rmsnorm_kernel<<<NTOK, 256>>>(p_x2, norm_w, p_xn3, HH, HH);

    // 16. lm head -> d_out [NTOK, 16384]
    gemm_nt_kernel<<<dim3(VV / GBN, NTOK / GBM, 1), 256>>>(
        p_xn3, lm_w, out, nullptr, NTOK, VV, HH, 0, 0, 0, 0, 1.f);
}